// round 13
// baseline (speedup 1.0000x reference)
#include <cuda_runtime.h>
#include <math.h>

#define DD     64
#define TRI    2080          // 64*65/2
#define NT     128           // threads per SYRK block
#define CHUNK  32            // nodes per smem chunk (was 16)
#define RSTRIDE 68           // padded row stride (floats)

#define MAX_M  100000
#define MAX_G  1024

// scratch (no allocations allowed)
__device__ float g_imp[MAX_M];      // imp, then sqrt(e) after k_softmax
__device__ float g_invd[MAX_G];     // 1/denom per graph
__device__ int   g_start[MAX_G + 1];

// ---------------------------------------------------------------------------
// Kernel 0: segment boundaries from sorted batch.
// Warp-cooperative dtype sniff (lanes 0-7 sample one odd word each);
// predecessor via shfl_up (only lane 0 loads batch[m-1]).
// ---------------------------------------------------------------------------
__global__ void k_bounds(const void* __restrict__ batch, int M, int G) {
    const int* b32 = (const int*)batch;
    const long long* b64 = (const long long*)batch;

    int m    = blockIdx.x * blockDim.x + threadIdx.x;
    int lane = threadIdx.x & 31;

    // ---- sniff (whole warp participates; no divergent return yet) ----
    int nz = 0;
    if (lane < 8) {
        int idx = (int)(((long long)M * (8 + lane)) / 16) | 1;
        if (idx >= M) idx = (M - 1) | 1;
        if (idx >= M) idx -= 2;
        if (idx >= 1 && idx < M) nz = (__ldg(b32 + idx) != 0);
    }
    int is64 = !__any_sync(0xFFFFFFFFu, nz);

    // ---- main load (clamped so every lane participates in shfl) ----
    int mm = (m < M) ? m : (M - 1);
    int b  = is64 ? (int)b64[mm] : b32[mm];
    int bprev = __shfl_up_sync(0xFFFFFFFFu, b, 1);

    if (m >= M) return;

    int pb;
    if (m == 0)          pb = -1;
    else if (lane == 0)  pb = is64 ? (int)b64[m - 1] : b32[m - 1];
    else                 pb = bprev;

    if (b  < 0) b  = 0; if (b  >= G) b  = G - 1;
    if (pb < -1) pb = -1; if (pb >= G) pb = G - 1;
    for (int g = pb + 1; g <= b; ++g) g_start[g] = m;
    if (m == M - 1) {
        for (int g = b + 1; g <= G; ++g) g_start[g] = M;
    }
}

// ---------------------------------------------------------------------------
// Kernel 1: imp[m] = dot(x[m], w) + bias. One warp per node. (verbatim,
// measured at HBM roof ~3.3us)
// ---------------------------------------------------------------------------
__global__ void k_imp(const float* __restrict__ x, const float* __restrict__ w,
                      const float* __restrict__ bias, int M) {
    int gwarp = (blockIdx.x * blockDim.x + threadIdx.x) >> 5;
    int lane  = threadIdx.x & 31;
    if (gwarp >= M) return;
    const float* xr = x + (size_t)gwarp * DD;
    float v = xr[lane] * __ldg(w + lane) + xr[lane + 32] * __ldg(w + lane + 32);
#pragma unroll
    for (int o = 16; o; o >>= 1) v += __shfl_xor_sync(0xFFFFFFFFu, v, o);
    if (lane == 0) g_imp[gwarp] = v + __ldg(bias);
}

// ---------------------------------------------------------------------------
// Kernel 1.5: per-graph softmax stats. (verbatim r12)
// g_imp[s..s+n) := sqrt(e_k);  g_invd[g] := 1/denom.
// ---------------------------------------------------------------------------
__global__ __launch_bounds__(128)
void k_softmax(int G) {
    __shared__ float sred[4];
    __shared__ float sbr;
    int g    = blockIdx.x;
    int tid  = threadIdx.x;
    int lane = tid & 31;
    int wid  = tid >> 5;
    int s    = g_start[g];
    int n    = g_start[g + 1] - s;

    float mx = -3.402823466e38f;
    for (int i = tid; i < n; i += 128) mx = fmaxf(mx, g_imp[s + i]);
#pragma unroll
    for (int o = 16; o; o >>= 1) mx = fmaxf(mx, __shfl_xor_sync(0xFFFFFFFFu, mx, o));
    if (lane == 0) sred[wid] = mx;
    __syncthreads();
    if (tid == 0)
        sbr = fmaxf(fmaxf(sred[0], sred[1]), fmaxf(sred[2], sred[3]));
    __syncthreads();
    mx = sbr;

    float sum = 0.f;
    for (int i = tid; i < n; i += 128) {
        float sq = expf(0.5f * (g_imp[s + i] - mx));
        sum += sq * sq;
        g_imp[s + i] = sq;                 // same-thread RW, no race
    }
#pragma unroll
    for (int o = 16; o; o >>= 1) sum += __shfl_xor_sync(0xFFFFFFFFu, sum, o);
    if (lane == 0) sred[wid] = sum;
    __syncthreads();
    if (tid == 0) {
        float t = sred[0] + sred[1] + sred[2] + sred[3];
        g_invd[g] = (n > 0) ? (1.0f / t) : 0.0f;
    }
}

// ---------------------------------------------------------------------------
// Kernel 2: pure weighted SYRK per graph + triu writeout.
// r12 structure; single change: CHUNK 16 -> 32 (half the barriers and half
// the exposed-LDG events; loader 4 float4/thread).
// ---------------------------------------------------------------------------
__global__ __launch_bounds__(NT)
void k_syrk(const float* __restrict__ x, float* __restrict__ out, int G) {
    __shared__ float sz[CHUNK * RSTRIDE];

    int g   = blockIdx.x;
    int tid = threadIdx.x;
    int s   = g_start[g];
    int n   = g_start[g + 1] - s;
    float inv_denom = g_invd[g];

    // ---- tile mapping: tid<72, tile = tid>>1 in [0,36), slice = tid&1 ----
    bool isComp = (tid < 72);
    int  tile   = tid >> 1;
    int  slice  = tid & 1;
    int  ti = 0, tmp = tile;
#pragma unroll
    for (int r = 0; r < 8; ++r) {
        int rl = 8 - r;
        if (ti == r && tmp >= rl) { tmp -= rl; ti = r + 1; }
    }
    int tj = ti + tmp;

    float acc[8][8];
#pragma unroll
    for (int i = 0; i < 8; ++i)
#pragma unroll
        for (int j = 0; j < 8; ++j) acc[i][j] = 0.f;

    // ---- main loop over node chunks (single-buffered, sqrt(e) at load) ----
    for (int c0 = 0; c0 < n; c0 += CHUNK) {
        __syncthreads();   // previous chunk's compute done before overwrite
#pragma unroll
        for (int q = tid; q < CHUNK * 16; q += NT) {
            int row = q >> 4, c4 = q & 15;
            float4 v = make_float4(0.f, 0.f, 0.f, 0.f);
            int node = c0 + row;
            if (node < n) {
                float sq = g_imp[s + node];            // sqrt(e_node)
                v = __ldg((const float4*)(x + ((size_t)(s + node) << 6)) + c4);
                v.x *= sq; v.y *= sq; v.z *= sq; v.w *= sq;
            }
            *(float4*)&sz[row * RSTRIDE + c4 * 4] = v;
        }
        __syncthreads();

        if (isComp) {
#pragma unroll 2
            for (int k = 0; k < CHUNK / 2; ++k) {
                int kk = 2 * k + slice;
                const float* row = &sz[kk * RSTRIDE];
                float4 a0 = *(const float4*)&row[ti * 8];
                float4 a1 = *(const float4*)&row[ti * 8 + 4];
                float4 b0 = *(const float4*)&row[tj * 8];
                float4 b1 = *(const float4*)&row[tj * 8 + 4];
                float a[8] = { a0.x, a0.y, a0.z, a0.w, a1.x, a1.y, a1.z, a1.w };
                float b[8] = { b0.x, b0.y, b0.z, b0.w, b1.x, b1.y, b1.z, b1.w };
#pragma unroll
                for (int i = 0; i < 8; ++i)
#pragma unroll
                    for (int j = 0; j < 8; ++j)
                        acc[i][j] += a[i] * b[j];
            }
        }
    }

    // ---- combine slices (pairs are adjacent lanes in same warp) + writeout ----
    if (isComp) {
        unsigned msk = (tid < 64) ? 0xFFFFFFFFu : 0x000000FFu;
#pragma unroll
        for (int i = 0; i < 8; ++i)
#pragma unroll
            for (int j = 0; j < 8; ++j)
                acc[i][j] += __shfl_xor_sync(msk, acc[i][j], 1);

        if (slice == 0) {
            float* og = out + (size_t)g * TRI;
#pragma unroll
            for (int i = 0; i < 8; ++i) {
                int gi = ti * 8 + i;
                int base = gi * DD - (gi * (gi - 1)) / 2 - gi;  // + gj -> triu idx
#pragma unroll
                for (int j = 0; j < 8; ++j) {
                    int gj = tj * 8 + j;
                    if (gj >= gi) og[base + gj] = acc[i][j] * inv_denom;
                }
            }
        }
    }
}

// ---------------------------------------------------------------------------
// Launch. Inputs identified BY SIZE (order-invariant):
//   att_b: size 1; att_w: size 64; batch: size*64 == size of x; edge: leftover.
// ---------------------------------------------------------------------------
extern "C" void kernel_launch(void* const* d_in, const int* in_sizes, int n_in,
                              void* d_out, int out_size) {
    int ib = -1, iw = -1, ibatch = -1, ix = -1;
    for (int i = 0; i < n_in; ++i) {
        if (in_sizes[i] == 1)       ib = i;
        else if (in_sizes[i] == DD) iw = i;
    }
    for (int i = 0; i < n_in && ibatch < 0; ++i) {
        if (i == ib || i == iw) continue;
        for (int j = 0; j < n_in; ++j) {
            if (j == i || j == ib || j == iw) continue;
            if ((long long)in_sizes[i] * DD == (long long)in_sizes[j]) {
                ibatch = i; ix = j; break;
            }
        }
    }
    if (ib < 0 || iw < 0 || ibatch < 0 || ix < 0) {  // fallback: reference order
        ix = 0; iw = 1; ib = 2; ibatch = 3;
    }

    const float* x    = (const float*)d_in[ix];
    const float* w    = (const float*)d_in[iw];
    const float* bias = (const float*)d_in[ib];
    const void*  batch = d_in[ibatch];

    int M = in_sizes[ix] / DD;
    int G = out_size / TRI;
    float* out = (float*)d_out;

    k_bounds<<<(M + 255) / 256, 256>>>(batch, M, G);
    k_imp<<<(M * 32 + 255) / 256, 256>>>(x, w, bias, M);
    k_softmax<<<G, 128>>>(G);
    k_syrk<<<G, NT>>>(x, out, G);
}

// round 14
// speedup vs baseline: 1.1021x; 1.1021x over previous
#include <cuda_runtime.h>
#include <math.h>

#define DD     64
#define TRI    2080          // 64*65/2
#define NT     128           // threads per SYRK block
#define CHUNK  16            // nodes per smem chunk (r12 proven best)
#define RSTRIDE 68           // padded row stride (floats)

#define MAX_M  100000
#define MAX_G  1024

// scratch (no allocations allowed)
__device__ float g_imp[MAX_M];      // imp, then sqrt(e) after k_softmax
__device__ float g_invd[MAX_G];     // 1/denom per graph
__device__ int   g_start[MAX_G + 1];

// ---------------------------------------------------------------------------
// Kernel 0: segment boundaries from sorted batch. (r13 — neutral, kept)
// ---------------------------------------------------------------------------
__global__ void k_bounds(const void* __restrict__ batch, int M, int G) {
    const int* b32 = (const int*)batch;
    const long long* b64 = (const long long*)batch;

    int m    = blockIdx.x * blockDim.x + threadIdx.x;
    int lane = threadIdx.x & 31;

    int nz = 0;
    if (lane < 8) {
        int idx = (int)(((long long)M * (8 + lane)) / 16) | 1;
        if (idx >= M) idx = (M - 1) | 1;
        if (idx >= M) idx -= 2;
        if (idx >= 1 && idx < M) nz = (__ldg(b32 + idx) != 0);
    }
    int is64 = !__any_sync(0xFFFFFFFFu, nz);

    int mm = (m < M) ? m : (M - 1);
    int b  = is64 ? (int)b64[mm] : b32[mm];
    int bprev = __shfl_up_sync(0xFFFFFFFFu, b, 1);

    if (m >= M) return;

    int pb;
    if (m == 0)          pb = -1;
    else if (lane == 0)  pb = is64 ? (int)b64[m - 1] : b32[m - 1];
    else                 pb = bprev;

    if (b  < 0) b  = 0; if (b  >= G) b  = G - 1;
    if (pb < -1) pb = -1; if (pb >= G) pb = G - 1;
    for (int g = pb + 1; g <= b; ++g) g_start[g] = m;
    if (m == M - 1) {
        for (int g = b + 1; g <= G; ++g) g_start[g] = M;
    }
}

// ---------------------------------------------------------------------------
// Kernel 1: imp[m] = dot(x[m], w) + bias. One warp per node. (verbatim)
// ---------------------------------------------------------------------------
__global__ void k_imp(const float* __restrict__ x, const float* __restrict__ w,
                      const float* __restrict__ bias, int M) {
    int gwarp = (blockIdx.x * blockDim.x + threadIdx.x) >> 5;
    int lane  = threadIdx.x & 31;
    if (gwarp >= M) return;
    const float* xr = x + (size_t)gwarp * DD;
    float v = xr[lane] * __ldg(w + lane) + xr[lane + 32] * __ldg(w + lane + 32);
#pragma unroll
    for (int o = 16; o; o >>= 1) v += __shfl_xor_sync(0xFFFFFFFFu, v, o);
    if (lane == 0) g_imp[gwarp] = v + __ldg(bias);
}

// ---------------------------------------------------------------------------
// Kernel 1.5: per-graph softmax stats. (verbatim r12)
// ---------------------------------------------------------------------------
__global__ __launch_bounds__(128)
void k_softmax(int G) {
    __shared__ float sred[4];
    __shared__ float sbr;
    int g    = blockIdx.x;
    int tid  = threadIdx.x;
    int lane = tid & 31;
    int wid  = tid >> 5;
    int s    = g_start[g];
    int n    = g_start[g + 1] - s;

    float mx = -3.402823466e38f;
    for (int i = tid; i < n; i += 128) mx = fmaxf(mx, g_imp[s + i]);
#pragma unroll
    for (int o = 16; o; o >>= 1) mx = fmaxf(mx, __shfl_xor_sync(0xFFFFFFFFu, mx, o));
    if (lane == 0) sred[wid] = mx;
    __syncthreads();
    if (tid == 0)
        sbr = fmaxf(fmaxf(sred[0], sred[1]), fmaxf(sred[2], sred[3]));
    __syncthreads();
    mx = sbr;

    float sum = 0.f;
    for (int i = tid; i < n; i += 128) {
        float sq = expf(0.5f * (g_imp[s + i] - mx));
        sum += sq * sq;
        g_imp[s + i] = sq;                 // same-thread RW, no race
    }
#pragma unroll
    for (int o = 16; o; o >>= 1) sum += __shfl_xor_sync(0xFFFFFFFFu, sum, o);
    if (lane == 0) sred[wid] = sum;
    __syncthreads();
    if (tid == 0) {
        float t = sred[0] + sred[1] + sred[2] + sred[3];
        g_invd[g] = (n > 0) ? (1.0f / t) : 0.0f;
    }
}

// ---------------------------------------------------------------------------
// Kernel 2: pure weighted SYRK per graph + triu writeout.
// r12 structure (CHUNK=16, single-buffered, sqrt(e) at load). Single change:
// heterogeneous slice packing — warps 0-1: tiles 0-31 x 2 slices (unchanged);
// warp 2: tiles 32-35 x 8 slices (all 32 lanes alive, 1/4 the FFMA issue).
// ---------------------------------------------------------------------------
__global__ __launch_bounds__(NT)
void k_syrk(const float* __restrict__ x, float* __restrict__ out, int G) {
    __shared__ float sz[CHUNK * RSTRIDE];

    int g   = blockIdx.x;
    int tid = threadIdx.x;
    int s   = g_start[g];
    int n   = g_start[g + 1] - s;
    float inv_denom = g_invd[g];

    // ---- heterogeneous tile mapping ----
    int tile, slice;
    if (tid < 64)      { tile = tid >> 1;              slice = tid & 1; }
    else if (tid < 96) { int tt = tid - 64; tile = 32 + (tt >> 3); slice = tt & 7; }
    else               { tile = 0;                     slice = 0; }   // loader-only

    int ti = 0, tmp = tile;
#pragma unroll
    for (int r = 0; r < 8; ++r) {
        int rl = 8 - r;
        if (ti == r && tmp >= rl) { tmp -= rl; ti = r + 1; }
    }
    int tj = ti + tmp;

    float acc[8][8];
#pragma unroll
    for (int i = 0; i < 8; ++i)
#pragma unroll
        for (int j = 0; j < 8; ++j) acc[i][j] = 0.f;

#define FFMA_BLOB(KK)                                                          \
    do {                                                                       \
        const float* row = &sz[(KK) * RSTRIDE];                                \
        float4 a0 = *(const float4*)&row[ti * 8];                              \
        float4 a1 = *(const float4*)&row[ti * 8 + 4];                          \
        float4 b0 = *(const float4*)&row[tj * 8];                              \
        float4 b1 = *(const float4*)&row[tj * 8 + 4];                          \
        float a[8] = { a0.x, a0.y, a0.z, a0.w, a1.x, a1.y, a1.z, a1.w };       \
        float b[8] = { b0.x, b0.y, b0.z, b0.w, b1.x, b1.y, b1.z, b1.w };       \
        _Pragma("unroll")                                                      \
        for (int i = 0; i < 8; ++i)                                            \
            _Pragma("unroll")                                                  \
            for (int j = 0; j < 8; ++j)                                        \
                acc[i][j] += a[i] * b[j];                                      \
    } while (0)

    // ---- main loop over node chunks (single-buffered, sqrt(e) at load) ----
    for (int c0 = 0; c0 < n; c0 += CHUNK) {
        __syncthreads();   // previous chunk's compute done before overwrite
#pragma unroll
        for (int q = tid; q < CHUNK * 16; q += NT) {
            int row = q >> 4, c4 = q & 15;
            float4 v = make_float4(0.f, 0.f, 0.f, 0.f);
            int node = c0 + row;
            if (node < n) {
                float sq = g_imp[s + node];            // sqrt(e_node)
                v = __ldg((const float4*)(x + ((size_t)(s + node) << 6)) + c4);
                v.x *= sq; v.y *= sq; v.z *= sq; v.w *= sq;
            }
            *(float4*)&sz[row * RSTRIDE + c4 * 4] = v;
        }
        __syncthreads();

        if (tid < 64) {                       // warps 0-1: 2 slices, 8 k each
#pragma unroll 2
            for (int k = 0; k < CHUNK / 2; ++k)
                FFMA_BLOB(2 * k + slice);
        } else if (tid < 96) {                // warp 2: 8 slices, 2 k each
#pragma unroll
            for (int k = 0; k < CHUNK / 8; ++k)
                FFMA_BLOB(8 * k + slice);
        }
    }

    // ---- slice combine + triu writeout ----
    if (tid < 64) {
#pragma unroll
        for (int i = 0; i < 8; ++i)
#pragma unroll
            for (int j = 0; j < 8; ++j)
                acc[i][j] += __shfl_xor_sync(0xFFFFFFFFu, acc[i][j], 1);
    } else if (tid < 96) {
#pragma unroll
        for (int i = 0; i < 8; ++i)
#pragma unroll
            for (int j = 0; j < 8; ++j) {
                acc[i][j] += __shfl_xor_sync(0xFFFFFFFFu, acc[i][j], 1);
                acc[i][j] += __shfl_xor_sync(0xFFFFFFFFu, acc[i][j], 2);
                acc[i][j] += __shfl_xor_sync(0xFFFFFFFFu, acc[i][j], 4);
            }
    }

    if (tid < 96 && slice == 0) {
        float* og = out + (size_t)g * TRI;
#pragma unroll
        for (int i = 0; i < 8; ++i) {
            int gi = ti * 8 + i;
            int base = gi * DD - (gi * (gi - 1)) / 2 - gi;  // + gj -> triu idx
#pragma unroll
            for (int j = 0; j < 8; ++j) {
                int gj = tj * 8 + j;
                if (gj >= gi) og[base + gj] = acc[i][j] * inv_denom;
            }
        }
    }
#undef FFMA_BLOB
}

// ---------------------------------------------------------------------------
// Launch. Inputs identified BY SIZE (order-invariant):
//   att_b: size 1; att_w: size 64; batch: size*64 == size of x; edge: leftover.
// ---------------------------------------------------------------------------
extern "C" void kernel_launch(void* const* d_in, const int* in_sizes, int n_in,
                              void* d_out, int out_size) {
    int ib = -1, iw = -1, ibatch = -1, ix = -1;
    for (int i = 0; i < n_in; ++i) {
        if (in_sizes[i] == 1)       ib = i;
        else if (in_sizes[i] == DD) iw = i;
    }
    for (int i = 0; i < n_in && ibatch < 0; ++i) {
        if (i == ib || i == iw) continue;
        for (int j = 0; j < n_in; ++j) {
            if (j == i || j == ib || j == iw) continue;
            if ((long long)in_sizes[i] * DD == (long long)in_sizes[j]) {
                ibatch = i; ix = j; break;
            }
        }
    }
    if (ib < 0 || iw < 0 || ibatch < 0 || ix < 0) {  // fallback: reference order
        ix = 0; iw = 1; ib = 2; ibatch = 3;
    }

    const float* x    = (const float*)d_in[ix];
    const float* w    = (const float*)d_in[iw];
    const float* bias = (const float*)d_in[ib];
    const void*  batch = d_in[ibatch];

    int M = in_sizes[ix] / DD;
    int G = out_size / TRI;
    float* out = (float*)d_out;

    k_bounds<<<(M + 255) / 256, 256>>>(batch, M, G);
    k_imp<<<(M * 32 + 255) / 256, 256>>>(x, w, bias, M);
    k_softmax<<<G, 128>>>(G);
    k_syrk<<<G, NT>>>(x, out, G);
}

// round 15
// speedup vs baseline: 1.1097x; 1.0069x over previous
#include <cuda_runtime.h>
#include <math.h>

#define DD     64
#define TRI    2080          // 64*65/2
#define NT     128           // threads per SYRK block
#define CHUNK  16            // nodes per smem chunk (r12 proven best)
#define RSTRIDE 68           // padded row stride (floats)

#define MAX_M  100000
#define MAX_G  1024

// scratch (no allocations allowed)
__device__ float g_imp[MAX_M];      // imp, then sqrt(e) after k_softmax
__device__ float g_invd[MAX_G];     // 1/denom per graph
__device__ int   g_start[MAX_G + 1];

// ---------------------------------------------------------------------------
// Kernel 0: segment boundaries from sorted batch. (verbatim r13)
// ---------------------------------------------------------------------------
__global__ void k_bounds(const void* __restrict__ batch, int M, int G) {
    const int* b32 = (const int*)batch;
    const long long* b64 = (const long long*)batch;

    int m    = blockIdx.x * blockDim.x + threadIdx.x;
    int lane = threadIdx.x & 31;

    int nz = 0;
    if (lane < 8) {
        int idx = (int)(((long long)M * (8 + lane)) / 16) | 1;
        if (idx >= M) idx = (M - 1) | 1;
        if (idx >= M) idx -= 2;
        if (idx >= 1 && idx < M) nz = (__ldg(b32 + idx) != 0);
    }
    int is64 = !__any_sync(0xFFFFFFFFu, nz);

    int mm = (m < M) ? m : (M - 1);
    int b  = is64 ? (int)b64[mm] : b32[mm];
    int bprev = __shfl_up_sync(0xFFFFFFFFu, b, 1);

    if (m >= M) return;

    int pb;
    if (m == 0)          pb = -1;
    else if (lane == 0)  pb = is64 ? (int)b64[m - 1] : b32[m - 1];
    else                 pb = bprev;

    if (b  < 0) b  = 0; if (b  >= G) b  = G - 1;
    if (pb < -1) pb = -1; if (pb >= G) pb = G - 1;
    for (int g = pb + 1; g <= b; ++g) g_start[g] = m;
    if (m == M - 1) {
        for (int g = b + 1; g <= G; ++g) g_start[g] = M;
    }
}

// ---------------------------------------------------------------------------
// Kernel 1: imp[m] = dot(x[m], w) + bias. One warp per node. (verbatim)
// ---------------------------------------------------------------------------
__global__ void k_imp(const float* __restrict__ x, const float* __restrict__ w,
                      const float* __restrict__ bias, int M) {
    int gwarp = (blockIdx.x * blockDim.x + threadIdx.x) >> 5;
    int lane  = threadIdx.x & 31;
    if (gwarp >= M) return;
    const float* xr = x + (size_t)gwarp * DD;
    float v = xr[lane] * __ldg(w + lane) + xr[lane + 32] * __ldg(w + lane + 32);
#pragma unroll
    for (int o = 16; o; o >>= 1) v += __shfl_xor_sync(0xFFFFFFFFu, v, o);
    if (lane == 0) g_imp[gwarp] = v + __ldg(bias);
}

// ---------------------------------------------------------------------------
// Kernel 1.5: per-graph softmax stats. (verbatim r12)
// ---------------------------------------------------------------------------
__global__ __launch_bounds__(128)
void k_softmax(int G) {
    __shared__ float sred[4];
    __shared__ float sbr;
    int g    = blockIdx.x;
    int tid  = threadIdx.x;
    int lane = tid & 31;
    int wid  = tid >> 5;
    int s    = g_start[g];
    int n    = g_start[g + 1] - s;

    float mx = -3.402823466e38f;
    for (int i = tid; i < n; i += 128) mx = fmaxf(mx, g_imp[s + i]);
#pragma unroll
    for (int o = 16; o; o >>= 1) mx = fmaxf(mx, __shfl_xor_sync(0xFFFFFFFFu, mx, o));
    if (lane == 0) sred[wid] = mx;
    __syncthreads();
    if (tid == 0)
        sbr = fmaxf(fmaxf(sred[0], sred[1]), fmaxf(sred[2], sred[3]));
    __syncthreads();
    mx = sbr;

    float sum = 0.f;
    for (int i = tid; i < n; i += 128) {
        float sq = expf(0.5f * (g_imp[s + i] - mx));
        sum += sq * sq;
        g_imp[s + i] = sq;                 // same-thread RW, no race
    }
#pragma unroll
    for (int o = 16; o; o >>= 1) sum += __shfl_xor_sync(0xFFFFFFFFu, sum, o);
    if (lane == 0) sred[wid] = sum;
    __syncthreads();
    if (tid == 0) {
        float t = sred[0] + sred[1] + sred[2] + sred[3];
        g_invd[g] = (n > 0) ? (1.0f / t) : 0.0f;
    }
}

// ---------------------------------------------------------------------------
// Kernel 2: pure weighted SYRK per graph + triu writeout.
// r14 structure (heterogeneous packing). Single change: __launch_bounds__
// min-blocks=5 to cap regs at 102 and restore the 5th resident block/SM.
// ---------------------------------------------------------------------------
__global__ __launch_bounds__(NT, 5)
void k_syrk(const float* __restrict__ x, float* __restrict__ out, int G) {
    __shared__ float sz[CHUNK * RSTRIDE];

    int g   = blockIdx.x;
    int tid = threadIdx.x;
    int s   = g_start[g];
    int n   = g_start[g + 1] - s;
    float inv_denom = g_invd[g];

    // ---- heterogeneous tile mapping ----
    int tile, slice;
    if (tid < 64)      { tile = tid >> 1;              slice = tid & 1; }
    else if (tid < 96) { int tt = tid - 64; tile = 32 + (tt >> 3); slice = tt & 7; }
    else               { tile = 0;                     slice = 0; }   // loader-only

    int ti = 0, tmp = tile;
#pragma unroll
    for (int r = 0; r < 8; ++r) {
        int rl = 8 - r;
        if (ti == r && tmp >= rl) { tmp -= rl; ti = r + 1; }
    }
    int tj = ti + tmp;

    float acc[8][8];
#pragma unroll
    for (int i = 0; i < 8; ++i)
#pragma unroll
        for (int j = 0; j < 8; ++j) acc[i][j] = 0.f;

#define FFMA_BLOB(KK)                                                          \
    do {                                                                       \
        const float* row = &sz[(KK) * RSTRIDE];                                \
        float4 a0 = *(const float4*)&row[ti * 8];                              \
        float4 a1 = *(const float4*)&row[ti * 8 + 4];                          \
        float4 b0 = *(const float4*)&row[tj * 8];                              \
        float4 b1 = *(const float4*)&row[tj * 8 + 4];                          \
        float a[8] = { a0.x, a0.y, a0.z, a0.w, a1.x, a1.y, a1.z, a1.w };       \
        float b[8] = { b0.x, b0.y, b0.z, b0.w, b1.x, b1.y, b1.z, b1.w };       \
        _Pragma("unroll")                                                      \
        for (int i = 0; i < 8; ++i)                                            \
            _Pragma("unroll")                                                  \
            for (int j = 0; j < 8; ++j)                                        \
                acc[i][j] += a[i] * b[j];                                      \
    } while (0)

    // ---- main loop over node chunks (single-buffered, sqrt(e) at load) ----
    for (int c0 = 0; c0 < n; c0 += CHUNK) {
        __syncthreads();   // previous chunk's compute done before overwrite
#pragma unroll
        for (int q = tid; q < CHUNK * 16; q += NT) {
            int row = q >> 4, c4 = q & 15;
            float4 v = make_float4(0.f, 0.f, 0.f, 0.f);
            int node = c0 + row;
            if (node < n) {
                float sq = g_imp[s + node];            // sqrt(e_node)
                v = __ldg((const float4*)(x + ((size_t)(s + node) << 6)) + c4);
                v.x *= sq; v.y *= sq; v.z *= sq; v.w *= sq;
            }
            *(float4*)&sz[row * RSTRIDE + c4 * 4] = v;
        }
        __syncthreads();

        if (tid < 64) {                       // warps 0-1: 2 slices, 8 k each
#pragma unroll 2
            for (int k = 0; k < CHUNK / 2; ++k)
                FFMA_BLOB(2 * k + slice);
        } else if (tid < 96) {                // warp 2: 8 slices, 2 k each
#pragma unroll
            for (int k = 0; k < CHUNK / 8; ++k)
                FFMA_BLOB(8 * k + slice);
        }
    }

    // ---- slice combine + triu writeout ----
    if (tid < 64) {
#pragma unroll
        for (int i = 0; i < 8; ++i)
#pragma unroll
            for (int j = 0; j < 8; ++j)
                acc[i][j] += __shfl_xor_sync(0xFFFFFFFFu, acc[i][j], 1);
    } else if (tid < 96) {
#pragma unroll
        for (int i = 0; i < 8; ++i)
#pragma unroll
            for (int j = 0; j < 8; ++j) {
                acc[i][j] += __shfl_xor_sync(0xFFFFFFFFu, acc[i][j], 1);
                acc[i][j] += __shfl_xor_sync(0xFFFFFFFFu, acc[i][j], 2);
                acc[i][j] += __shfl_xor_sync(0xFFFFFFFFu, acc[i][j], 4);
            }
    }

    if (tid < 96 && slice == 0) {
        float* og = out + (size_t)g * TRI;
#pragma unroll
        for (int i = 0; i < 8; ++i) {
            int gi = ti * 8 + i;
            int base = gi * DD - (gi * (gi - 1)) / 2 - gi;  // + gj -> triu idx
#pragma unroll
            for (int j = 0; j < 8; ++j) {
                int gj = tj * 8 + j;
                if (gj >= gi) og[base + gj] = acc[i][j] * inv_denom;
            }
        }
    }
#undef FFMA_BLOB
}

// ---------------------------------------------------------------------------
// Launch. Inputs identified BY SIZE (order-invariant):
//   att_b: size 1; att_w: size 64; batch: size*64 == size of x; edge: leftover.
// ---------------------------------------------------------------------------
extern "C" void kernel_launch(void* const* d_in, const int* in_sizes, int n_in,
                              void* d_out, int out_size) {
    int ib = -1, iw = -1, ibatch = -1, ix = -1;
    for (int i = 0; i < n_in; ++i) {
        if (in_sizes[i] == 1)       ib = i;
        else if (in_sizes[i] == DD) iw = i;
    }
    for (int i = 0; i < n_in && ibatch < 0; ++i) {
        if (i == ib || i == iw) continue;
        for (int j = 0; j < n_in; ++j) {
            if (j == i || j == ib || j == iw) continue;
            if ((long long)in_sizes[i] * DD == (long long)in_sizes[j]) {
                ibatch = i; ix = j; break;
            }
        }
    }
    if (ib < 0 || iw < 0 || ibatch < 0 || ix < 0) {  // fallback: reference order
        ix = 0; iw = 1; ib = 2; ibatch = 3;
    }

    const float* x    = (const float*)d_in[ix];
    const float* w    = (const float*)d_in[iw];
    const float* bias = (const float*)d_in[ib];
    const void*  batch = d_in[ibatch];

    int M = in_sizes[ix] / DD;
    int G = out_size / TRI;
    float* out = (float*)d_out;

    k_bounds<<<(M + 255) / 256, 256>>>(batch, M, G);
    k_imp<<<(M * 32 + 255) / 256, 256>>>(x, w, bias, M);
    k_softmax<<<G, 128>>>(G);
    k_syrk<<<G, NT>>>(x, out, G);
}